// round 6
// baseline (speedup 1.0000x reference)
#include <cuda_runtime.h>
#include <math.h>

#define TP 98
typedef unsigned long long ull;

__device__ __align__(16) float g_xn[96*96*96];
__device__ __align__(16) float g_M[8*96*96];
__device__ __align__(16) float g_N[8*96*96];
__device__ __align__(16) float g_u[8*96];
__device__ __align__(16) float g_w[8*96];
__device__ __align__(16) float g_cc[8];
__device__ __align__(16) float g_bp[96];
__device__ __align__(16) float g_part[8*96*96*96];

__device__ __forceinline__ ull pack2(float a) {
    ull r; asm("mov.b64 %0, {%1, %2};" : "=l"(r) : "f"(a), "f"(a)); return r;
}
__device__ __forceinline__ ull pk2(float a, float b) {
    ull r; asm("mov.b64 %0, {%1, %2};" : "=l"(r) : "f"(a), "f"(b)); return r;
}
__device__ __forceinline__ ull fma2(ull a, ull b, ull c) {
    ull d; asm("fma.rn.f32x2 %0, %1, %2, %3;" : "=l"(d) : "l"(a), "l"(b), "l"(c)); return d;
}
__device__ __forceinline__ float2 unpk(ull p) {
    float2 f; asm("mov.b64 {%0, %1}, %2;" : "=f"(f.x), "=f"(f.y) : "l"(p)); return f;
}

// 96x96x96 GEMM microkernel: 256 thr (16x16), 6x6/thread, f32x2 accumulators.
// AMODE 0: A(i,k)=A[k*TP+i] ; AMODE 1: A(i,k)=A[i*96+k]. B pitch = PB.
template<int AMODE, int PB>
__device__ __forceinline__ void gemm96(const float* __restrict__ A,
                                       const float* __restrict__ B,
                                       int i0, int j0, ull acc[6][3]) {
    const float* Bj = B + j0;
#pragma unroll 2
    for (int k = 0; k < 96; k += 2) {
        ull b0[3], b1[3];
#pragma unroll
        for (int p = 0; p < 3; ++p) {
            b0[p] = *(const ull*)(Bj + k * PB + 2 * p);
            b1[p] = *(const ull*)(Bj + (k + 1) * PB + 2 * p);
        }
        ull a0[6], a1[6];
        if (AMODE == 0) {
#pragma unroll
            for (int ii = 0; ii < 3; ++ii) {
                float2 f0 = *(const float2*)(A + k * TP + i0 + 2 * ii);
                float2 f1 = *(const float2*)(A + (k + 1) * TP + i0 + 2 * ii);
                a0[2*ii] = pack2(f0.x); a0[2*ii+1] = pack2(f0.y);
                a1[2*ii] = pack2(f1.x); a1[2*ii+1] = pack2(f1.y);
            }
        } else {
#pragma unroll
            for (int i = 0; i < 6; ++i) {
                float2 f = *(const float2*)(A + (i0 + i) * 96 + k);
                a0[i] = pack2(f.x); a1[i] = pack2(f.y);
            }
        }
#pragma unroll
        for (int i = 0; i < 6; ++i)
#pragma unroll
            for (int p = 0; p < 3; ++p)
                acc[i][p] = fma2(a0[i], b0[p], acc[i][p]);
#pragma unroll
        for (int i = 0; i < 6; ++i)
#pragma unroll
            for (int p = 0; p < 3; ++p)
                acc[i][p] = fma2(a1[i], b1[p], acc[i][p]);
    }
}

// ---- 1) GroupNorm (static smem only, high occupancy)
__global__ void gn_kernel(const float* __restrict__ x,
                          const float* __restrict__ gamma,
                          const float* __restrict__ beta) {
    const int b = blockIdx.x, g = blockIdx.y, tid = threadIdx.x;
    const float* xp = x + b * 9216 + g * 1152;
    float vals[9], sum = 0.f, sq = 0.f;
#pragma unroll
    for (int t = 0; t < 9; ++t) {
        float v = xp[tid + t * 128];
        vals[t] = v; sum += v; sq += v * v;
    }
    __shared__ float s1[128], s2[128];
    s1[tid] = sum; s2[tid] = sq;
    __syncthreads();
    for (int o = 64; o > 0; o >>= 1) {
        if (tid < o) { s1[tid] += s1[tid + o]; s2[tid] += s2[tid + o]; }
        __syncthreads();
    }
    const float mean = s1[0] * (1.f / 1152.f);
    const float var  = s2[0] * (1.f / 1152.f) - mean * mean;
    const float rstd = rsqrtf(var + 1e-5f);
#pragma unroll
    for (int t = 0; t < 9; ++t) {
        int e = tid + t * 128;
        int ch = g * 12 + e / 96;
        g_xn[b * 9216 + g * 1152 + e] = (vals[t] - mean) * rstd * gamma[ch] + beta[ch];
    }
}

// ---- 2) Precompute. grid (8 heads, 2): y=0 -> M,u,w,c,(b'); y=1 -> N
__global__ __launch_bounds__(256, 1)
void pre_kernel(const float* __restrict__ Wq, const float* __restrict__ bq,
                const float* __restrict__ Wk, const float* __restrict__ bk,
                const float* __restrict__ Wv, const float* __restrict__ bv,
                const float* __restrict__ Wo, const float* __restrict__ bo) {
    const int h = blockIdx.x, m = blockIdx.y, tid = threadIdx.x;
    extern __shared__ float sm[];
    float* bufA = sm;           // 9216
    float* bufB = sm + 9216;    // 9408 (pitch TP when transposed)
    const float inv = rsqrtf(96.0f);
    const int tx = tid & 15, ty = tid >> 4;
    const int i0 = ty * 6, j0 = tx * 6;

    if (m == 0) {
        for (int idx = tid; idx < 9216; idx += 256) {
            int i = idx / 96, d = idx % 96;
            bufA[idx]         = Wq[i * 768 + h * 96 + d];
            bufB[d * TP + i]  = Wk[i * 768 + h * 96 + d];
        }
        __syncthreads();
        ull acc[6][3];
#pragma unroll
        for (int i = 0; i < 6; ++i) for (int p = 0; p < 3; ++p) acc[i][p] = 0ULL;
        gemm96<1, TP>(bufA, bufB, i0, j0, acc);   // M = Wq_h Wk_h^T
#pragma unroll
        for (int i = 0; i < 6; ++i)
#pragma unroll
            for (int p = 0; p < 3; ++p) {
                float2 f = unpk(acc[i][p]);
                g_M[h * 9216 + (i0 + i) * 96 + j0 + 2 * p]     = f.x * inv;
                g_M[h * 9216 + (i0 + i) * 96 + j0 + 2 * p + 1] = f.y * inv;
            }
        if (tid < 96) {
            float a = 0.f, c = 0.f;
            for (int d = 0; d < 96; ++d) {
                a += bufA[tid * 96 + d] * bk[h * 96 + d];
                c += bufB[d * TP + tid] * bq[h * 96 + d];
            }
            g_u[h * 96 + tid] = a * inv;
            g_w[h * 96 + tid] = c * inv;
        }
        if (tid == 0) {
            float cs = 0.f;
            for (int d = 0; d < 96; ++d) cs += bq[h * 96 + d] * bk[h * 96 + d];
            g_cc[h] = cs * inv;
        }
        if (h == 0 && tid >= 128 && tid < 224) {
            int c = tid - 128;
            float s = bo[c];
            for (int j = 0; j < 768; ++j) s += bv[j] * Wo[j * 96 + c];
            g_bp[c] = s;
        }
    } else {
        for (int idx = tid; idx < 9216; idx += 256) {
            int i = idx / 96, d = idx % 96;
            bufA[idx] = Wv[i * 768 + h * 96 + d];
            bufB[idx] = Wo[h * 9216 + idx];
        }
        __syncthreads();
        ull acc[6][3];
#pragma unroll
        for (int i = 0; i < 6; ++i) for (int p = 0; p < 3; ++p) acc[i][p] = 0ULL;
        gemm96<1, 96>(bufA, bufB, i0, j0, acc);   // N = Wv_h Wo_h
#pragma unroll
        for (int i = 0; i < 6; ++i)
#pragma unroll
            for (int p = 0; p < 3; ++p)
                *(ull*)(g_N + h * 9216 + (i0 + i) * 96 + j0 + 2 * p) = acc[i][p];
    }
}

// ---- 3) Attention per (b,h), occ=2, 3-buffer schedule
__global__ __launch_bounds__(256, 2)
void attn_kernel() {
    const int b = blockIdx.x, h = blockIdx.y;
    extern __shared__ float sm[];
    float* tT = sm;                 // 96 x TP ; later reused for X2 (pitch 96)
    float* Wb = sm + 96 * TP;       // M, later N
    float* Yb = Wb + 9216;          // X1, later P
    float* rv = Yb + 9216;
    float* zv = rv + 96;
    float* uv = zv + 96;
    float* wv = uv + 96;
    const int tid = threadIdx.x;
    const int tx = tid & 15, ty = tid >> 4;
    const int i0 = ty * 6, j0 = tx * 6;
    const float NEGINF = __int_as_float(0xff800000);

    {
        const float* xb = g_xn + b * 9216;
        for (int idx = tid; idx < 9216; idx += 256) {
            int s = idx / 96, c = idx % 96;
            tT[c * TP + s] = xb[idx];
            Wb[idx] = g_M[h * 9216 + idx];
        }
        if (tid < 96) { uv[tid] = g_u[h * 96 + tid]; wv[tid] = g_w[h * 96 + tid]; }
    }
    __syncthreads();

    if (tid < 96) {
        float a = 0.f;
        for (int c = 0; c < 96; ++c) a += tT[c * TP + tid] * uv[c];
        rv[tid] = a;
    } else if (tid < 192) {
        const int j = tid - 96;
        float a = 0.f;
        for (int c = 0; c < 96; ++c) a += tT[c * TP + j] * wv[c];
        zv[j] = a;
    }
    {
        ull acc[6][3];
#pragma unroll
        for (int i = 0; i < 6; ++i) for (int p = 0; p < 3; ++p) acc[i][p] = 0ULL;
        gemm96<0, 96>(tT, Wb, i0, j0, acc);        // X1 = t * M
#pragma unroll
        for (int i = 0; i < 6; ++i)
#pragma unroll
            for (int p = 0; p < 3; ++p)
                *(ull*)(Yb + (i0 + i) * 96 + j0 + 2 * p) = acc[i][p];
    }
    __syncthreads();

    for (int idx = tid; idx < 9216; idx += 256) Wb[idx] = g_N[h * 9216 + idx];
    float sv[6][6];
    {
        const float cc = g_cc[h];
        ull acc[6][3];
#pragma unroll
        for (int i = 0; i < 6; ++i) for (int p = 0; p < 3; ++p) acc[i][p] = 0ULL;
        gemm96<1, TP>(Yb, tT, i0, j0, acc);        // S = X1 * t^T
#pragma unroll
        for (int i = 0; i < 6; ++i)
#pragma unroll
            for (int p = 0; p < 3; ++p) {
                float2 f = unpk(acc[i][p]);
                sv[i][2 * p] = f.x; sv[i][2 * p + 1] = f.y;
            }
#pragma unroll
        for (int i = 0; i < 6; ++i) {
            const int ig = i0 + i;
            const float ri = rv[ig] + cc;
            float mx = NEGINF;
#pragma unroll
            for (int j = 0; j < 6; ++j) {
                const int jg = j0 + j;
                float v = sv[i][j] + ri + zv[jg];
                v = (jg <= ig) ? v : NEGINF;
                sv[i][j] = v;
                mx = fmaxf(mx, v);
            }
#pragma unroll
            for (int d = 1; d < 16; d <<= 1)
                mx = fmaxf(mx, __shfl_xor_sync(0xffffffffu, mx, d));
            float s = 0.f;
#pragma unroll
            for (int j = 0; j < 6; ++j) {
                float e = __expf(sv[i][j] - mx);
                sv[i][j] = e; s += e;
            }
#pragma unroll
            for (int d = 1; d < 16; d <<= 1)
                s += __shfl_xor_sync(0xffffffffu, s, d);
            const float is = 1.0f / s;
#pragma unroll
            for (int j = 0; j < 6; ++j) sv[i][j] *= is;
        }
    }
    __syncthreads();

    {
#pragma unroll
        for (int i = 0; i < 6; ++i)
#pragma unroll
            for (int p = 0; p < 3; ++p)
                *(ull*)(Yb + (i0 + i) * 96 + j0 + 2 * p) = pk2(sv[i][2*p], sv[i][2*p+1]);
        ull acc[6][3];
#pragma unroll
        for (int i = 0; i < 6; ++i) for (int p = 0; p < 3; ++p) acc[i][p] = 0ULL;
        gemm96<0, 96>(tT, Wb, i0, j0, acc);        // X2 = t * N (in regs)
        __syncthreads();
#pragma unroll
        for (int i = 0; i < 6; ++i)
#pragma unroll
            for (int p = 0; p < 3; ++p)
                *(ull*)(tT + (i0 + i) * 96 + j0 + 2 * p) = acc[i][p];
    }
    __syncthreads();

    {
        ull acc[6][3];
#pragma unroll
        for (int i = 0; i < 6; ++i) for (int p = 0; p < 3; ++p) acc[i][p] = 0ULL;
        gemm96<1, 96>(Yb, tT, i0, j0, acc);        // AV = P * X2
        float* dst = g_part + (h * 96 + b) * 9216;
#pragma unroll
        for (int i = 0; i < 6; ++i)
#pragma unroll
            for (int p = 0; p < 3; ++p)
                *(ull*)(dst + (i0 + i) * 96 + j0 + 2 * p) = acc[i][p];
    }
}

// ---- 4) Fused head-reduction + broadcast residual add
// out[b,j,s,l] = sum_h part[h,j,s,l] + bp[l] + xn[b,j,l]
// grid (96 j, 2 s-half), 384 threads. smem: O-sum slab (18KB) + xn slab (36KB).
__global__ __launch_bounds__(384)
void redbc_kernel(float* __restrict__ out) {
    extern __shared__ float smf[];
    float4* Os4 = (float4*)smf;            // [48][24] float4 = 4608 floats
    float4* Xs4 = (float4*)(smf + 4608);   // [96][24] float4 = 9216 floats
    const int j = blockIdx.x, sh = blockIdx.y;
    const int tid = threadIdx.x;

    // stage xn[b, j, l] -> Xs4[b*24 + q]
#pragma unroll
    for (int r = 0; r < 6; ++r) {
        int idx = tid + r * 384;           // 2304 float4s
        int b = idx / 24, q = idx - b * 24;
        Xs4[idx] = *(const float4*)(g_xn + (size_t)b * 9216 + j * 96 + q * 4);
    }
    // stage sum_h part[h, j, sh*48+s, l] + bp -> Os4[s*24 + q]
#pragma unroll
    for (int r = 0; r < 3; ++r) {
        int idx = tid + r * 384;           // 1152 float4s
        int s = idx / 24, q = idx - s * 24;
        size_t off = (size_t)j * 9216 + (size_t)(sh * 48 + s) * 96 + q * 4;
        float4 a = ((const float4*)g_bp)[q];
#pragma unroll
        for (int h = 0; h < 8; ++h) {
            float4 p = *(const float4*)(g_part + (size_t)h * 884736 + off);
            a.x += p.x; a.y += p.y; a.z += p.z; a.w += p.w;
        }
        Os4[idx] = a;
    }
    __syncthreads();

    const int s_i = tid / 24, q = tid - s_i * 24;   // s_i 0..15, q 0..23
    const float4 o0 = Os4[s_i * 24 + q];
    const float4 o1 = Os4[(s_i + 16) * 24 + q];
    const float4 o2 = Os4[(s_i + 32) * 24 + q];
    float* dst = out + (size_t)j * 9216 + (size_t)(sh * 48) * 96 + q * 4;
#pragma unroll 4
    for (int b = 0; b < 96; ++b) {
        float4 xv = Xs4[b * 24 + q];
        float* d0 = dst + (size_t)b * 884736 + s_i * 96;
        __stcs((float4*)(d0),            make_float4(o0.x + xv.x, o0.y + xv.y, o0.z + xv.z, o0.w + xv.w));
        __stcs((float4*)(d0 + 16 * 96),  make_float4(o1.x + xv.x, o1.y + xv.y, o1.z + xv.z, o1.w + xv.w));
        __stcs((float4*)(d0 + 32 * 96),  make_float4(o2.x + xv.x, o2.y + xv.y, o2.z + xv.z, o2.w + xv.w));
    }
}

extern "C" void kernel_launch(void* const* d_in, const int* in_sizes, int n_in,
                              void* d_out, int out_size) {
    const float* x     = (const float*)d_in[0];
    const float* Wq    = (const float*)d_in[1];
    const float* bq    = (const float*)d_in[2];
    const float* Wk    = (const float*)d_in[3];
    const float* bk    = (const float*)d_in[4];
    const float* Wv    = (const float*)d_in[5];
    const float* bv    = (const float*)d_in[6];
    const float* Wo    = (const float*)d_in[7];
    const float* bo    = (const float*)d_in[8];
    const float* gamma = (const float*)d_in[9];
    const float* beta  = (const float*)d_in[10];
    float* out = (float*)d_out;

    const int pre_smem   = (9216 + 96 * TP) * 4;
    const int attn_smem  = (96 * TP + 9216 * 2 + 4 * 96) * 4;   // 112,896 B
    const int redbc_smem = (4608 + 9216) * 4;                    // 55,296 B
    cudaFuncSetAttribute(pre_kernel,   cudaFuncAttributeMaxDynamicSharedMemorySize, pre_smem);
    cudaFuncSetAttribute(attn_kernel,  cudaFuncAttributeMaxDynamicSharedMemorySize, attn_smem);
    cudaFuncSetAttribute(redbc_kernel, cudaFuncAttributeMaxDynamicSharedMemorySize, redbc_smem);

    gn_kernel<<<dim3(96, 8), 128>>>(x, gamma, beta);
    pre_kernel<<<dim3(8, 2), 256, pre_smem>>>(Wq, bq, Wk, bk, Wv, bv, Wo, bo);
    attn_kernel<<<dim3(96, 8), 256, attn_smem>>>();
    redbc_kernel<<<dim3(96, 2), 384, redbc_smem>>>(out);
}

// round 7
// speedup vs baseline: 1.0659x; 1.0659x over previous
#include <cuda_runtime.h>
#include <math.h>

#define TP 98
typedef unsigned long long ull;

__device__ __align__(16) float g_xn[96*96*96];
__device__ __align__(16) float g_M[8*96*96];
__device__ __align__(16) float g_N[8*96*96];
__device__ __align__(16) float g_u[8*96];
__device__ __align__(16) float g_w[8*96];
__device__ __align__(16) float g_cc[8];
__device__ __align__(16) float g_bp[96];
__device__ __align__(16) float g_part[8*96*96*96];
__device__ __align__(16) float g_O[96*96*96];

__device__ __forceinline__ ull pack2(float a) {
    ull r; asm("mov.b64 %0, {%1, %2};" : "=l"(r) : "f"(a), "f"(a)); return r;
}
__device__ __forceinline__ ull pk2(float a, float b) {
    ull r; asm("mov.b64 %0, {%1, %2};" : "=l"(r) : "f"(a), "f"(b)); return r;
}
__device__ __forceinline__ ull fma2(ull a, ull b, ull c) {
    ull d; asm("fma.rn.f32x2 %0, %1, %2, %3;" : "=l"(d) : "l"(a), "l"(b), "l"(c)); return d;
}
__device__ __forceinline__ float2 unpk(ull p) {
    float2 f; asm("mov.b64 {%0, %1}, %2;" : "=f"(f.x), "=f"(f.y) : "l"(p)); return f;
}

// 96x96x96 GEMM microkernel: 256 thr (16x16), 6x6/thread, f32x2 accumulators.
// AMODE 0: A(i,k)=A[k*TP+i] ; AMODE 1: A(i,k)=A[i*96+k]. B pitch = PB.
template<int AMODE, int PB>
__device__ __forceinline__ void gemm96(const float* __restrict__ A,
                                       const float* __restrict__ B,
                                       int i0, int j0, ull acc[6][3]) {
    const float* Bj = B + j0;
#pragma unroll 2
    for (int k = 0; k < 96; k += 2) {
        ull b0[3], b1[3];
#pragma unroll
        for (int p = 0; p < 3; ++p) {
            b0[p] = *(const ull*)(Bj + k * PB + 2 * p);
            b1[p] = *(const ull*)(Bj + (k + 1) * PB + 2 * p);
        }
        ull a0[6], a1[6];
        if (AMODE == 0) {
#pragma unroll
            for (int ii = 0; ii < 3; ++ii) {
                float2 f0 = *(const float2*)(A + k * TP + i0 + 2 * ii);
                float2 f1 = *(const float2*)(A + (k + 1) * TP + i0 + 2 * ii);
                a0[2*ii] = pack2(f0.x); a0[2*ii+1] = pack2(f0.y);
                a1[2*ii] = pack2(f1.x); a1[2*ii+1] = pack2(f1.y);
            }
        } else {
#pragma unroll
            for (int i = 0; i < 6; ++i) {
                float2 f = *(const float2*)(A + (i0 + i) * 96 + k);
                a0[i] = pack2(f.x); a1[i] = pack2(f.y);
            }
        }
#pragma unroll
        for (int i = 0; i < 6; ++i)
#pragma unroll
            for (int p = 0; p < 3; ++p)
                acc[i][p] = fma2(a0[i], b0[p], acc[i][p]);
#pragma unroll
        for (int i = 0; i < 6; ++i)
#pragma unroll
            for (int p = 0; p < 3; ++p)
                acc[i][p] = fma2(a1[i], b1[p], acc[i][p]);
    }
}

// ---- 1) GroupNorm (static smem only, high occupancy)
__global__ void gn_kernel(const float* __restrict__ x,
                          const float* __restrict__ gamma,
                          const float* __restrict__ beta) {
    const int b = blockIdx.x, g = blockIdx.y, tid = threadIdx.x;
    const float* xp = x + b * 9216 + g * 1152;
    float vals[9], sum = 0.f, sq = 0.f;
#pragma unroll
    for (int t = 0; t < 9; ++t) {
        float v = xp[tid + t * 128];
        vals[t] = v; sum += v; sq += v * v;
    }
    __shared__ float s1[128], s2[128];
    s1[tid] = sum; s2[tid] = sq;
    __syncthreads();
    for (int o = 64; o > 0; o >>= 1) {
        if (tid < o) { s1[tid] += s1[tid + o]; s2[tid] += s2[tid + o]; }
        __syncthreads();
    }
    const float mean = s1[0] * (1.f / 1152.f);
    const float var  = s2[0] * (1.f / 1152.f) - mean * mean;
    const float rstd = rsqrtf(var + 1e-5f);
#pragma unroll
    for (int t = 0; t < 9; ++t) {
        int e = tid + t * 128;
        int ch = g * 12 + e / 96;
        g_xn[b * 9216 + g * 1152 + e] = (vals[t] - mean) * rstd * gamma[ch] + beta[ch];
    }
}

// ---- 2) Precompute. grid (8 heads, 2): y=0 -> M,u,w,c,(b'); y=1 -> N
__global__ __launch_bounds__(256, 1)
void pre_kernel(const float* __restrict__ Wq, const float* __restrict__ bq,
                const float* __restrict__ Wk, const float* __restrict__ bk,
                const float* __restrict__ Wv, const float* __restrict__ bv,
                const float* __restrict__ Wo, const float* __restrict__ bo) {
    const int h = blockIdx.x, m = blockIdx.y, tid = threadIdx.x;
    extern __shared__ float sm[];
    float* bufA = sm;           // 9216
    float* bufB = sm + 9216;    // 9408 (pitch TP when transposed)
    const float inv = rsqrtf(96.0f);
    const int tx = tid & 15, ty = tid >> 4;
    const int i0 = ty * 6, j0 = tx * 6;

    if (m == 0) {
        for (int idx = tid; idx < 9216; idx += 256) {
            int i = idx / 96, d = idx % 96;
            bufA[idx]         = Wq[i * 768 + h * 96 + d];
            bufB[d * TP + i]  = Wk[i * 768 + h * 96 + d];
        }
        __syncthreads();
        ull acc[6][3];
#pragma unroll
        for (int i = 0; i < 6; ++i) for (int p = 0; p < 3; ++p) acc[i][p] = 0ULL;
        gemm96<1, TP>(bufA, bufB, i0, j0, acc);   // M = Wq_h Wk_h^T
#pragma unroll
        for (int i = 0; i < 6; ++i)
#pragma unroll
            for (int p = 0; p < 3; ++p) {
                float2 f = unpk(acc[i][p]);
                g_M[h * 9216 + (i0 + i) * 96 + j0 + 2 * p]     = f.x * inv;
                g_M[h * 9216 + (i0 + i) * 96 + j0 + 2 * p + 1] = f.y * inv;
            }
        if (tid < 96) {
            float a = 0.f, c = 0.f;
            for (int d = 0; d < 96; ++d) {
                a += bufA[tid * 96 + d] * bk[h * 96 + d];
                c += bufB[d * TP + tid] * bq[h * 96 + d];
            }
            g_u[h * 96 + tid] = a * inv;
            g_w[h * 96 + tid] = c * inv;
        }
        if (tid == 0) {
            float cs = 0.f;
            for (int d = 0; d < 96; ++d) cs += bq[h * 96 + d] * bk[h * 96 + d];
            g_cc[h] = cs * inv;
        }
        if (h == 0 && tid >= 128 && tid < 224) {
            int c = tid - 128;
            float s = bo[c];
            for (int j = 0; j < 768; ++j) s += bv[j] * Wo[j * 96 + c];
            g_bp[c] = s;
        }
    } else {
        for (int idx = tid; idx < 9216; idx += 256) {
            int i = idx / 96, d = idx % 96;
            bufA[idx] = Wv[i * 768 + h * 96 + d];
            bufB[idx] = Wo[h * 9216 + idx];
        }
        __syncthreads();
        ull acc[6][3];
#pragma unroll
        for (int i = 0; i < 6; ++i) for (int p = 0; p < 3; ++p) acc[i][p] = 0ULL;
        gemm96<1, 96>(bufA, bufB, i0, j0, acc);   // N = Wv_h Wo_h
#pragma unroll
        for (int i = 0; i < 6; ++i)
#pragma unroll
            for (int p = 0; p < 3; ++p)
                *(ull*)(g_N + h * 9216 + (i0 + i) * 96 + j0 + 2 * p) = acc[i][p];
    }
}

// ---- 3) Attention per (b,h), occ=2, 3-buffer schedule
__global__ __launch_bounds__(256, 2)
void attn_kernel() {
    const int b = blockIdx.x, h = blockIdx.y;
    extern __shared__ float sm[];
    float* tT = sm;                 // 96 x TP ; later reused for X2 (pitch 96)
    float* Wb = sm + 96 * TP;       // M, later N
    float* Yb = Wb + 9216;          // X1, later P
    float* rv = Yb + 9216;
    float* zv = rv + 96;
    float* uv = zv + 96;
    float* wv = uv + 96;
    const int tid = threadIdx.x;
    const int tx = tid & 15, ty = tid >> 4;
    const int i0 = ty * 6, j0 = tx * 6;
    const float NEGINF = __int_as_float(0xff800000);

    {
        const float* xb = g_xn + b * 9216;
        for (int idx = tid; idx < 9216; idx += 256) {
            int s = idx / 96, c = idx % 96;
            tT[c * TP + s] = xb[idx];
            Wb[idx] = g_M[h * 9216 + idx];
        }
        if (tid < 96) { uv[tid] = g_u[h * 96 + tid]; wv[tid] = g_w[h * 96 + tid]; }
    }
    __syncthreads();

    if (tid < 96) {
        float a = 0.f;
        for (int c = 0; c < 96; ++c) a += tT[c * TP + tid] * uv[c];
        rv[tid] = a;
    } else if (tid < 192) {
        const int j = tid - 96;
        float a = 0.f;
        for (int c = 0; c < 96; ++c) a += tT[c * TP + j] * wv[c];
        zv[j] = a;
    }
    {
        ull acc[6][3];
#pragma unroll
        for (int i = 0; i < 6; ++i) for (int p = 0; p < 3; ++p) acc[i][p] = 0ULL;
        gemm96<0, 96>(tT, Wb, i0, j0, acc);        // X1 = t * M
#pragma unroll
        for (int i = 0; i < 6; ++i)
#pragma unroll
            for (int p = 0; p < 3; ++p)
                *(ull*)(Yb + (i0 + i) * 96 + j0 + 2 * p) = acc[i][p];
    }
    __syncthreads();

    for (int idx = tid; idx < 9216; idx += 256) Wb[idx] = g_N[h * 9216 + idx];
    float sv[6][6];
    {
        const float cc = g_cc[h];
        ull acc[6][3];
#pragma unroll
        for (int i = 0; i < 6; ++i) for (int p = 0; p < 3; ++p) acc[i][p] = 0ULL;
        gemm96<1, TP>(Yb, tT, i0, j0, acc);        // S = X1 * t^T
#pragma unroll
        for (int i = 0; i < 6; ++i)
#pragma unroll
            for (int p = 0; p < 3; ++p) {
                float2 f = unpk(acc[i][p]);
                sv[i][2 * p] = f.x; sv[i][2 * p + 1] = f.y;
            }
#pragma unroll
        for (int i = 0; i < 6; ++i) {
            const int ig = i0 + i;
            const float ri = rv[ig] + cc;
            float mx = NEGINF;
#pragma unroll
            for (int j = 0; j < 6; ++j) {
                const int jg = j0 + j;
                float v = sv[i][j] + ri + zv[jg];
                v = (jg <= ig) ? v : NEGINF;
                sv[i][j] = v;
                mx = fmaxf(mx, v);
            }
#pragma unroll
            for (int d = 1; d < 16; d <<= 1)
                mx = fmaxf(mx, __shfl_xor_sync(0xffffffffu, mx, d));
            float s = 0.f;
#pragma unroll
            for (int j = 0; j < 6; ++j) {
                float e = __expf(sv[i][j] - mx);
                sv[i][j] = e; s += e;
            }
#pragma unroll
            for (int d = 1; d < 16; d <<= 1)
                s += __shfl_xor_sync(0xffffffffu, s, d);
            const float is = 1.0f / s;
#pragma unroll
            for (int j = 0; j < 6; ++j) sv[i][j] *= is;
        }
    }
    __syncthreads();

    {
#pragma unroll
        for (int i = 0; i < 6; ++i)
#pragma unroll
            for (int p = 0; p < 3; ++p)
                *(ull*)(Yb + (i0 + i) * 96 + j0 + 2 * p) = pk2(sv[i][2*p], sv[i][2*p+1]);
        ull acc[6][3];
#pragma unroll
        for (int i = 0; i < 6; ++i) for (int p = 0; p < 3; ++p) acc[i][p] = 0ULL;
        gemm96<0, 96>(tT, Wb, i0, j0, acc);        // X2 = t * N (in regs)
        __syncthreads();
#pragma unroll
        for (int i = 0; i < 6; ++i)
#pragma unroll
            for (int p = 0; p < 3; ++p)
                *(ull*)(tT + (i0 + i) * 96 + j0 + 2 * p) = acc[i][p];
    }
    __syncthreads();

    {
        ull acc[6][3];
#pragma unroll
        for (int i = 0; i < 6; ++i) for (int p = 0; p < 3; ++p) acc[i][p] = 0ULL;
        gemm96<1, 96>(Yb, tT, i0, j0, acc);        // AV = P * X2
        float* dst = g_part + (h * 96 + b) * 9216;
#pragma unroll
        for (int i = 0; i < 6; ++i)
#pragma unroll
            for (int p = 0; p < 3; ++p)
                *(ull*)(dst + (i0 + i) * 96 + j0 + 2 * p) = acc[i][p];
    }
}

// ---- 4) Head reduction + bias (2 float4/thread)
__global__ void reduce_kernel() {
    const int base = blockIdx.x * 512 + threadIdx.x;
#pragma unroll
    for (int r = 0; r < 2; ++r) {
        const int idx = base + r * 256;
        float4 a = ((const float4*)g_bp)[idx % 24];
#pragma unroll
        for (int h = 0; h < 8; ++h) {
            float4 p = ((const float4*)g_part)[h * 221184 + idx];
            a.x += p.x; a.y += p.y; a.z += p.z; a.w += p.w;
        }
        ((float4*)g_O)[idx] = a;
    }
}

// ---- 5) Broadcast residual: out[b,j,s,l] = O[j,s,l] + xn[b,j,l]
// grid (6 btile, 96 j), 384 threads; per-thread (b_i,q) fixed; no div/mod in loop.
__global__ __launch_bounds__(384)
void bcast_kernel(float* __restrict__ out) {
    __shared__ __align__(16) float O_s[9216];
    const int bt = blockIdx.x, j = blockIdx.y;
    const int tid = threadIdx.x;
    const float4* Og = (const float4*)(g_O + j * 9216);
    float4* Os4 = (float4*)O_s;
#pragma unroll
    for (int r = 0; r < 6; ++r) Os4[tid + r * 384] = Og[tid + r * 384];
    const int b_i = tid / 24;       // 0..15
    const int q   = tid - b_i * 24; // 0..23
    const int bg  = bt * 16 + b_i;
    const float4 xnv = *(const float4*)(g_xn + (size_t)bg * 9216 + j * 96 + q * 4);
    __syncthreads();
    float* dst = out + ((size_t)bg * 96 + (size_t)j) * 9216 + q * 4;
#pragma unroll 8
    for (int s = 0; s < 96; ++s) {
        float4 o = Os4[s * 24 + q];
        float4 v = make_float4(o.x + xnv.x, o.y + xnv.y, o.z + xnv.z, o.w + xnv.w);
        __stcs((float4*)(dst + s * 96), v);
    }
}

extern "C" void kernel_launch(void* const* d_in, const int* in_sizes, int n_in,
                              void* d_out, int out_size) {
    const float* x     = (const float*)d_in[0];
    const float* Wq    = (const float*)d_in[1];
    const float* bq    = (const float*)d_in[2];
    const float* Wk    = (const float*)d_in[3];
    const float* bk    = (const float*)d_in[4];
    const float* Wv    = (const float*)d_in[5];
    const float* bv    = (const float*)d_in[6];
    const float* Wo    = (const float*)d_in[7];
    const float* bo    = (const float*)d_in[8];
    const float* gamma = (const float*)d_in[9];
    const float* beta  = (const float*)d_in[10];
    float* out = (float*)d_out;

    const int pre_smem  = (9216 + 96 * TP) * 4;
    const int attn_smem = (96 * TP + 9216 * 2 + 4 * 96) * 4;   // 112,896 B
    cudaFuncSetAttribute(pre_kernel,  cudaFuncAttributeMaxDynamicSharedMemorySize, pre_smem);
    cudaFuncSetAttribute(attn_kernel, cudaFuncAttributeMaxDynamicSharedMemorySize, attn_smem);

    gn_kernel<<<dim3(96, 8), 128>>>(x, gamma, beta);
    pre_kernel<<<dim3(8, 2), 256, pre_smem>>>(Wq, bq, Wk, bk, Wv, bv, Wo, bo);
    attn_kernel<<<dim3(96, 8), 256, attn_smem>>>();
    reduce_kernel<<<432, 256>>>();
    bcast_kernel<<<dim3(6, 96), 384>>>(out);
}

// round 8
// speedup vs baseline: 1.0880x; 1.0208x over previous
#include <cuda_runtime.h>
#include <math.h>

#define TP 98
typedef unsigned long long ull;

__device__ __align__(16) float g_xn[96*96*96];
__device__ __align__(16) float g_M[8*96*96];
__device__ __align__(16) float g_N[8*96*96];
__device__ __align__(16) float g_u[8*96];
__device__ __align__(16) float g_w[8*96];
__device__ __align__(16) float g_cc[8];
__device__ __align__(16) float g_bp[96];
__device__ __align__(16) float g_part[8*96*96*96];
__device__ __align__(16) float g_O[96*96*96];

__device__ __forceinline__ ull pack2(float a) {
    ull r; asm("mov.b64 %0, {%1, %2};" : "=l"(r) : "f"(a), "f"(a)); return r;
}
__device__ __forceinline__ ull pk2(float a, float b) {
    ull r; asm("mov.b64 %0, {%1, %2};" : "=l"(r) : "f"(a), "f"(b)); return r;
}
__device__ __forceinline__ ull fma2(ull a, ull b, ull c) {
    ull d; asm("fma.rn.f32x2 %0, %1, %2, %3;" : "=l"(d) : "l"(a), "l"(b), "l"(c)); return d;
}
__device__ __forceinline__ float2 unpk(ull p) {
    float2 f; asm("mov.b64 {%0, %1}, %2;" : "=f"(f.x), "=f"(f.y) : "l"(p)); return f;
}

// 96x96x96 GEMM microkernel: 256 thr (16x16), 6x6/thread, f32x2 accumulators.
// AMODE 0: A(i,k)=A[k*TP+i] ; AMODE 1: A(i,k)=A[i*96+k]. B pitch = PB.
template<int AMODE, int PB>
__device__ __forceinline__ void gemm96(const float* __restrict__ A,
                                       const float* __restrict__ B,
                                       int i0, int j0, ull acc[6][3]) {
    const float* Bj = B + j0;
#pragma unroll 2
    for (int k = 0; k < 96; k += 2) {
        ull b0[3], b1[3];
#pragma unroll
        for (int p = 0; p < 3; ++p) {
            b0[p] = *(const ull*)(Bj + k * PB + 2 * p);
            b1[p] = *(const ull*)(Bj + (k + 1) * PB + 2 * p);
        }
        ull a0[6], a1[6];
        if (AMODE == 0) {
#pragma unroll
            for (int ii = 0; ii < 3; ++ii) {
                float2 f0 = *(const float2*)(A + k * TP + i0 + 2 * ii);
                float2 f1 = *(const float2*)(A + (k + 1) * TP + i0 + 2 * ii);
                a0[2*ii] = pack2(f0.x); a0[2*ii+1] = pack2(f0.y);
                a1[2*ii] = pack2(f1.x); a1[2*ii+1] = pack2(f1.y);
            }
        } else {
#pragma unroll
            for (int i = 0; i < 6; ++i) {
                float2 f = *(const float2*)(A + (i0 + i) * 96 + k);
                a0[i] = pack2(f.x); a1[i] = pack2(f.y);
            }
        }
#pragma unroll
        for (int i = 0; i < 6; ++i)
#pragma unroll
            for (int p = 0; p < 3; ++p)
                acc[i][p] = fma2(a0[i], b0[p], acc[i][p]);
#pragma unroll
        for (int i = 0; i < 6; ++i)
#pragma unroll
            for (int p = 0; p < 3; ++p)
                acc[i][p] = fma2(a1[i], b1[p], acc[i][p]);
    }
}

// One fully-unrolled 12-k chunk (A row-major pitch 96, B pitch 96).
__device__ __forceinline__ void gemm12(const float* __restrict__ A,
                                       const float* __restrict__ B,
                                       int i0, int j0, int kbase, ull acc[6][3]) {
    const float* Bj = B + j0;
#pragma unroll
    for (int kk = 0; kk < 12; kk += 2) {
        const int k = kbase + kk;
        ull b0[3], b1[3];
#pragma unroll
        for (int p = 0; p < 3; ++p) {
            b0[p] = *(const ull*)(Bj + k * 96 + 2 * p);
            b1[p] = *(const ull*)(Bj + (k + 1) * 96 + 2 * p);
        }
        ull a0[6], a1[6];
#pragma unroll
        for (int i = 0; i < 6; ++i) {
            float2 f = *(const float2*)(A + (i0 + i) * 96 + k);
            a0[i] = pack2(f.x); a1[i] = pack2(f.y);
        }
#pragma unroll
        for (int i = 0; i < 6; ++i)
#pragma unroll
            for (int p = 0; p < 3; ++p)
                acc[i][p] = fma2(a0[i], b0[p], acc[i][p]);
#pragma unroll
        for (int i = 0; i < 6; ++i)
#pragma unroll
            for (int p = 0; p < 3; ++p)
                acc[i][p] = fma2(a1[i], b1[p], acc[i][p]);
    }
}

// ---- 1) GroupNorm (static smem only, high occupancy)
__global__ void gn_kernel(const float* __restrict__ x,
                          const float* __restrict__ gamma,
                          const float* __restrict__ beta) {
    const int b = blockIdx.x, g = blockIdx.y, tid = threadIdx.x;
    const float* xp = x + b * 9216 + g * 1152;
    float vals[9], sum = 0.f, sq = 0.f;
#pragma unroll
    for (int t = 0; t < 9; ++t) {
        float v = xp[tid + t * 128];
        vals[t] = v; sum += v; sq += v * v;
    }
    __shared__ float s1[128], s2[128];
    s1[tid] = sum; s2[tid] = sq;
    __syncthreads();
    for (int o = 64; o > 0; o >>= 1) {
        if (tid < o) { s1[tid] += s1[tid + o]; s2[tid] += s2[tid + o]; }
        __syncthreads();
    }
    const float mean = s1[0] * (1.f / 1152.f);
    const float var  = s2[0] * (1.f / 1152.f) - mean * mean;
    const float rstd = rsqrtf(var + 1e-5f);
#pragma unroll
    for (int t = 0; t < 9; ++t) {
        int e = tid + t * 128;
        int ch = g * 12 + e / 96;
        g_xn[b * 9216 + g * 1152 + e] = (vals[t] - mean) * rstd * gamma[ch] + beta[ch];
    }
}

// ---- 2) Precompute. grid (8 heads, 2): y=0 -> M,u,w,c,(b'); y=1 -> N
__global__ __launch_bounds__(256, 1)
void pre_kernel(const float* __restrict__ Wq, const float* __restrict__ bq,
                const float* __restrict__ Wk, const float* __restrict__ bk,
                const float* __restrict__ Wv, const float* __restrict__ bv,
                const float* __restrict__ Wo, const float* __restrict__ bo) {
    const int h = blockIdx.x, m = blockIdx.y, tid = threadIdx.x;
    extern __shared__ float sm[];
    float* bufA = sm;           // 9216
    float* bufB = sm + 9216;    // 9408 (pitch TP when transposed)
    const float inv = rsqrtf(96.0f);
    const int tx = tid & 15, ty = tid >> 4;
    const int i0 = ty * 6, j0 = tx * 6;

    if (m == 0) {
        for (int idx = tid; idx < 9216; idx += 256) {
            int i = idx / 96, d = idx % 96;
            bufA[idx]         = Wq[i * 768 + h * 96 + d];
            bufB[d * TP + i]  = Wk[i * 768 + h * 96 + d];
        }
        __syncthreads();
        ull acc[6][3];
#pragma unroll
        for (int i = 0; i < 6; ++i) for (int p = 0; p < 3; ++p) acc[i][p] = 0ULL;
        gemm96<1, TP>(bufA, bufB, i0, j0, acc);   // M = Wq_h Wk_h^T
#pragma unroll
        for (int i = 0; i < 6; ++i)
#pragma unroll
            for (int p = 0; p < 3; ++p) {
                float2 f = unpk(acc[i][p]);
                g_M[h * 9216 + (i0 + i) * 96 + j0 + 2 * p]     = f.x * inv;
                g_M[h * 9216 + (i0 + i) * 96 + j0 + 2 * p + 1] = f.y * inv;
            }
        if (tid < 96) {
            float a = 0.f, c = 0.f;
            for (int d = 0; d < 96; ++d) {
                a += bufA[tid * 96 + d] * bk[h * 96 + d];
                c += bufB[d * TP + tid] * bq[h * 96 + d];
            }
            g_u[h * 96 + tid] = a * inv;
            g_w[h * 96 + tid] = c * inv;
        }
        if (tid == 0) {
            float cs = 0.f;
            for (int d = 0; d < 96; ++d) cs += bq[h * 96 + d] * bk[h * 96 + d];
            g_cc[h] = cs * inv;
        }
        if (h == 0 && tid >= 128 && tid < 224) {
            int c = tid - 128;
            float s = bo[c];
            for (int j = 0; j < 768; ++j) s += bv[j] * Wo[j * 96 + c];
            g_bp[c] = s;
        }
    } else {
        for (int idx = tid; idx < 9216; idx += 256) {
            int i = idx / 96, d = idx % 96;
            bufA[idx] = Wv[i * 768 + h * 96 + d];
            bufB[idx] = Wo[h * 9216 + idx];
        }
        __syncthreads();
        ull acc[6][3];
#pragma unroll
        for (int i = 0; i < 6; ++i) for (int p = 0; p < 3; ++p) acc[i][p] = 0ULL;
        gemm96<1, 96>(bufA, bufB, i0, j0, acc);   // N = Wv_h Wo_h
#pragma unroll
        for (int i = 0; i < 6; ++i)
#pragma unroll
            for (int p = 0; p < 3; ++p)
                *(ull*)(g_N + h * 9216 + (i0 + i) * 96 + j0 + 2 * p) = acc[i][p];
    }
}

// ---- 3) Attention per (b,h), occ=2, 3-buffer schedule, chunked-causal GEMM4
__global__ __launch_bounds__(256, 2)
void attn_kernel() {
    const int b = blockIdx.x, h = blockIdx.y;
    extern __shared__ float sm[];
    float* tT = sm;                 // 96 x TP ; later reused for X2 (pitch 96)
    float* Wb = sm + 96 * TP;       // M, later N
    float* Yb = Wb + 9216;          // X1, later P
    float* rv = Yb + 9216;
    float* zv = rv + 96;
    float* uv = zv + 96;
    float* wv = uv + 96;
    const int tid = threadIdx.x;
    const int tx = tid & 15, ty = tid >> 4;
    const int i0 = ty * 6, j0 = tx * 6;
    const float NEGINF = __int_as_float(0xff800000);

    {
        const float* xb = g_xn + b * 9216;
        for (int idx = tid; idx < 9216; idx += 256) {
            int s = idx / 96, c = idx % 96;
            tT[c * TP + s] = xb[idx];
            Wb[idx] = g_M[h * 9216 + idx];
        }
        if (tid < 96) { uv[tid] = g_u[h * 96 + tid]; wv[tid] = g_w[h * 96 + tid]; }
    }
    __syncthreads();

    if (tid < 96) {
        float a = 0.f;
        for (int c = 0; c < 96; ++c) a += tT[c * TP + tid] * uv[c];
        rv[tid] = a;
    } else if (tid < 192) {
        const int j = tid - 96;
        float a = 0.f;
        for (int c = 0; c < 96; ++c) a += tT[c * TP + j] * wv[c];
        zv[j] = a;
    }
    {
        ull acc[6][3];
#pragma unroll
        for (int i = 0; i < 6; ++i) for (int p = 0; p < 3; ++p) acc[i][p] = 0ULL;
        gemm96<0, 96>(tT, Wb, i0, j0, acc);        // X1 = t * M
#pragma unroll
        for (int i = 0; i < 6; ++i)
#pragma unroll
            for (int p = 0; p < 3; ++p)
                *(ull*)(Yb + (i0 + i) * 96 + j0 + 2 * p) = acc[i][p];
    }
    __syncthreads();

    for (int idx = tid; idx < 9216; idx += 256) Wb[idx] = g_N[h * 9216 + idx];
    float sv[6][6];
    {
        const float cc = g_cc[h];
        ull acc[6][3];
#pragma unroll
        for (int i = 0; i < 6; ++i) for (int p = 0; p < 3; ++p) acc[i][p] = 0ULL;
        gemm96<1, TP>(Yb, tT, i0, j0, acc);        // S = X1 * t^T
#pragma unroll
        for (int i = 0; i < 6; ++i)
#pragma unroll
            for (int p = 0; p < 3; ++p) {
                float2 f = unpk(acc[i][p]);
                sv[i][2 * p] = f.x; sv[i][2 * p + 1] = f.y;
            }
#pragma unroll
        for (int i = 0; i < 6; ++i) {
            const int ig = i0 + i;
            const float ri = rv[ig] + cc;
            float mx = NEGINF;
#pragma unroll
            for (int j = 0; j < 6; ++j) {
                const int jg = j0 + j;
                float v = sv[i][j] + ri + zv[jg];
                v = (jg <= ig) ? v : NEGINF;
                sv[i][j] = v;
                mx = fmaxf(mx, v);
            }
#pragma unroll
            for (int d = 1; d < 16; d <<= 1)
                mx = fmaxf(mx, __shfl_xor_sync(0xffffffffu, mx, d));
            float s = 0.f;
#pragma unroll
            for (int j = 0; j < 6; ++j) {
                float e = __expf(sv[i][j] - mx);
                sv[i][j] = e; s += e;
            }
#pragma unroll
            for (int d = 1; d < 16; d <<= 1)
                s += __shfl_xor_sync(0xffffffffu, s, d);
            const float is = 1.0f / s;
#pragma unroll
            for (int j = 0; j < 6; ++j) sv[i][j] *= is;
        }
    }
    __syncthreads();

    {
#pragma unroll
        for (int i = 0; i < 6; ++i)
#pragma unroll
            for (int p = 0; p < 3; ++p)
                *(ull*)(Yb + (i0 + i) * 96 + j0 + 2 * p) = pk2(sv[i][2*p], sv[i][2*p+1]);
        ull acc[6][3];
#pragma unroll
        for (int i = 0; i < 6; ++i) for (int p = 0; p < 3; ++p) acc[i][p] = 0ULL;
        gemm96<0, 96>(tT, Wb, i0, j0, acc);        // X2 = t * N (in regs)
        __syncthreads();
#pragma unroll
        for (int i = 0; i < 6; ++i)
#pragma unroll
            for (int p = 0; p < 3; ++p)
                *(ull*)(tT + (i0 + i) * 96 + j0 + 2 * p) = acc[i][p];
    }
    __syncthreads();

    // GEMM4: AV = P * X2, causal k-truncation via unrolled 12-k chunks
    // (warp w owns rows 12w..12w+11; P[i][k]=0 for k>i, so k < 12(w+1) suffices)
    {
        const int klim = ((tid >> 5) + 1) * 12;
        ull acc[6][3];
#pragma unroll
        for (int i = 0; i < 6; ++i) for (int p = 0; p < 3; ++p) acc[i][p] = 0ULL;
        for (int kb = 0; kb < klim; kb += 12)
            gemm12(Yb, tT, i0, j0, kb, acc);
        float* dst = g_part + (h * 96 + b) * 9216;
#pragma unroll
        for (int i = 0; i < 6; ++i)
#pragma unroll
            for (int p = 0; p < 3; ++p)
                *(ull*)(dst + (i0 + i) * 96 + j0 + 2 * p) = acc[i][p];
    }
}

// ---- 4) Head reduction + bias (4 float4/thread, 512 threads)
__global__ void reduce_kernel() {
    const int base = blockIdx.x * 2048 + threadIdx.x;
#pragma unroll
    for (int r = 0; r < 4; ++r) {
        const int idx = base + r * 512;
        float4 a = ((const float4*)g_bp)[idx % 24];
#pragma unroll
        for (int h = 0; h < 8; ++h) {
            float4 p = ((const float4*)g_part)[h * 221184 + idx];
            a.x += p.x; a.y += p.y; a.z += p.z; a.w += p.w;
        }
        ((float4*)g_O)[idx] = a;
    }
}

// ---- 5) Broadcast residual: out[b,j,s,l] = O[j,s,l] + xn[b,j,l]
__global__ __launch_bounds__(384)
void bcast_kernel(float* __restrict__ out) {
    __shared__ __align__(16) float O_s[9216];
    const int bt = blockIdx.x, j = blockIdx.y;
    const int tid = threadIdx.x;
    const float4* Og = (const float4*)(g_O + j * 9216);
    float4* Os4 = (float4*)O_s;
#pragma unroll
    for (int r = 0; r < 6; ++r) Os4[tid + r * 384] = Og[tid + r * 384];
    const int b_i = tid / 24;       // 0..15
    const int q   = tid - b_i * 24; // 0..23
    const int bg  = bt * 16 + b_i;
    const float4 xnv = *(const float4*)(g_xn + (size_t)bg * 9216 + j * 96 + q * 4);
    __syncthreads();
    float* dst = out + ((size_t)bg * 96 + (size_t)j) * 9216 + q * 4;
#pragma unroll 8
    for (int s = 0; s < 96; ++s) {
        float4 o = Os4[s * 24 + q];
        float4 v = make_float4(o.x + xnv.x, o.y + xnv.y, o.z + xnv.z, o.w + xnv.w);
        __stcs((float4*)(dst + s * 96), v);
    }
}

extern "C" void kernel_launch(void* const* d_in, const int* in_sizes, int n_in,
                              void* d_out, int out_size) {
    const float* x     = (const float*)d_in[0];
    const float* Wq    = (const float*)d_in[1];
    const float* bq    = (const float*)d_in[2];
    const float* Wk    = (const float*)d_in[3];
    const float* bk    = (const float*)d_in[4];
    const float* Wv    = (const float*)d_in[5];
    const float* bv    = (const float*)d_in[6];
    const float* Wo    = (const float*)d_in[7];
    const float* bo    = (const float*)d_in[8];
    const float* gamma = (const float*)d_in[9];
    const float* beta  = (const float*)d_in[10];
    float* out = (float*)d_out;

    const int pre_smem  = (9216 + 96 * TP) * 4;
    const int attn_smem = (96 * TP + 9216 * 2 + 4 * 96) * 4;   // 112,896 B
    cudaFuncSetAttribute(pre_kernel,  cudaFuncAttributeMaxDynamicSharedMemorySize, pre_smem);
    cudaFuncSetAttribute(attn_kernel, cudaFuncAttributeMaxDynamicSharedMemorySize, attn_smem);

    gn_kernel<<<dim3(96, 8), 128>>>(x, gamma, beta);
    pre_kernel<<<dim3(8, 2), 256, pre_smem>>>(Wq, bq, Wk, bk, Wv, bv, Wo, bo);
    attn_kernel<<<dim3(96, 8), 256, attn_smem>>>();
    reduce_kernel<<<108, 512>>>();
    bcast_kernel<<<dim3(6, 96), 384>>>(out);
}

// round 9
// speedup vs baseline: 1.3746x; 1.2634x over previous
#include <cuda_runtime.h>
#include <math.h>

#define TP 98
#define PT 100
typedef unsigned long long ull;
typedef unsigned uint32;

__device__ __align__(16) float g_xn[96*96*96];
__device__ __align__(16) float g_M[8*96*96];   // transposed: [h][j][c] = M[c][j]
__device__ __align__(16) float g_N[8*96*96];   // transposed: [h][l][c] = N[c][l]
__device__ __align__(16) float g_u[8*96];
__device__ __align__(16) float g_w[8*96];
__device__ __align__(16) float g_cc[8];
__device__ __align__(16) float g_bp[96];
__device__ __align__(16) float g_part[8*96*96*96];
__device__ __align__(16) float g_O[96*96*96];

__device__ __forceinline__ ull pack2(float a) {
    ull r; asm("mov.b64 %0, {%1, %2};" : "=l"(r) : "f"(a), "f"(a)); return r;
}
__device__ __forceinline__ ull fma2(ull a, ull b, ull c) {
    ull d; asm("fma.rn.f32x2 %0, %1, %2, %3;" : "=l"(d) : "l"(a), "l"(b), "l"(c)); return d;
}
__device__ __forceinline__ float2 unpk(ull p) {
    float2 f; asm("mov.b64 {%0, %1}, %2;" : "=f"(f.x), "=f"(f.y) : "l"(p)); return f;
}
__device__ __forceinline__ uint32 f2tf(float f) {
    uint32 r; asm("cvt.rna.tf32.f32 %0, %1;" : "=r"(r) : "f"(f)); return r;
}
__device__ __forceinline__ void mma8(float c[4], uint32 a0, uint32 a1, uint32 a2, uint32 a3,
                                     uint32 b0, uint32 b1) {
    asm("mma.sync.aligned.m16n8k8.row.col.f32.tf32.tf32.f32 "
        "{%0,%1,%2,%3},{%4,%5,%6,%7},{%8,%9},{%0,%1,%2,%3};"
        : "+f"(c[0]), "+f"(c[1]), "+f"(c[2]), "+f"(c[3])
        : "r"(a0), "r"(a1), "r"(a2), "r"(a3), "r"(b0), "r"(b1));
}

// Warp GEMM: C(16x48) = A(rows r0..r0+15, k=0..95) x B([n][k] layout), both pitch PT.
__device__ __forceinline__ void wgemm(const uint32* __restrict__ A,
                                      const uint32* __restrict__ B,
                                      int r0, int c0, int lane, float c[6][4]) {
    const int g = lane >> 2, tg = lane & 3;
    const uint32* Ap = A + (r0 + g) * PT + tg;
    const uint32* Bp = B + (c0 + g) * PT + tg;
#pragma unroll
    for (int k8 = 0; k8 < 12; ++k8) {
        const int kb = k8 * 8;
        uint32 a0 = Ap[kb], a1 = Ap[8 * PT + kb], a2 = Ap[kb + 4], a3 = Ap[8 * PT + kb + 4];
#pragma unroll
        for (int n = 0; n < 6; ++n) {
            uint32 b0 = Bp[n * 8 * PT + kb], b1 = Bp[n * 8 * PT + kb + 4];
            mma8(c[n], a0, a1, a2, a3, b0, b1);
        }
    }
}

// FFMA2 GEMM for pre (unchanged machinery)
template<int AMODE, int PB>
__device__ __forceinline__ void gemm96(const float* __restrict__ A,
                                       const float* __restrict__ B,
                                       int i0, int j0, ull acc[6][3]) {
    const float* Bj = B + j0;
#pragma unroll 2
    for (int k = 0; k < 96; k += 2) {
        ull b0[3], b1[3];
#pragma unroll
        for (int p = 0; p < 3; ++p) {
            b0[p] = *(const ull*)(Bj + k * PB + 2 * p);
            b1[p] = *(const ull*)(Bj + (k + 1) * PB + 2 * p);
        }
        ull a0[6], a1[6];
        if (AMODE == 0) {
#pragma unroll
            for (int ii = 0; ii < 3; ++ii) {
                float2 f0 = *(const float2*)(A + k * TP + i0 + 2 * ii);
                float2 f1 = *(const float2*)(A + (k + 1) * TP + i0 + 2 * ii);
                a0[2*ii] = pack2(f0.x); a0[2*ii+1] = pack2(f0.y);
                a1[2*ii] = pack2(f1.x); a1[2*ii+1] = pack2(f1.y);
            }
        } else {
#pragma unroll
            for (int i = 0; i < 6; ++i) {
                float2 f = *(const float2*)(A + (i0 + i) * 96 + k);
                a0[i] = pack2(f.x); a1[i] = pack2(f.y);
            }
        }
#pragma unroll
        for (int i = 0; i < 6; ++i)
#pragma unroll
            for (int p = 0; p < 3; ++p)
                acc[i][p] = fma2(a0[i], b0[p], acc[i][p]);
#pragma unroll
        for (int i = 0; i < 6; ++i)
#pragma unroll
            for (int p = 0; p < 3; ++p)
                acc[i][p] = fma2(a1[i], b1[p], acc[i][p]);
    }
}

// ---- 1) GroupNorm
__global__ void gn_kernel(const float* __restrict__ x,
                          const float* __restrict__ gamma,
                          const float* __restrict__ beta) {
    const int b = blockIdx.x, g = blockIdx.y, tid = threadIdx.x;
    const float* xp = x + b * 9216 + g * 1152;
    float vals[9], sum = 0.f, sq = 0.f;
#pragma unroll
    for (int t = 0; t < 9; ++t) {
        float v = xp[tid + t * 128];
        vals[t] = v; sum += v; sq += v * v;
    }
    __shared__ float s1[128], s2[128];
    s1[tid] = sum; s2[tid] = sq;
    __syncthreads();
    for (int o = 64; o > 0; o >>= 1) {
        if (tid < o) { s1[tid] += s1[tid + o]; s2[tid] += s2[tid + o]; }
        __syncthreads();
    }
    const float mean = s1[0] * (1.f / 1152.f);
    const float var  = s2[0] * (1.f / 1152.f) - mean * mean;
    const float rstd = rsqrtf(var + 1e-5f);
#pragma unroll
    for (int t = 0; t < 9; ++t) {
        int e = tid + t * 128;
        int ch = g * 12 + e / 96;
        g_xn[b * 9216 + g * 1152 + e] = (vals[t] - mean) * rstd * gamma[ch] + beta[ch];
    }
}

// ---- 2) Precompute (writes M^T and N^T for the mma B-layout)
__global__ __launch_bounds__(256, 1)
void pre_kernel(const float* __restrict__ Wq, const float* __restrict__ bq,
                const float* __restrict__ Wk, const float* __restrict__ bk,
                const float* __restrict__ Wv, const float* __restrict__ bv,
                const float* __restrict__ Wo, const float* __restrict__ bo) {
    const int h = blockIdx.x, m = blockIdx.y, tid = threadIdx.x;
    extern __shared__ float sm[];
    float* bufA = sm;
    float* bufB = sm + 9216;
    const float inv = rsqrtf(96.0f);
    const int tx = tid & 15, ty = tid >> 4;
    const int i0 = ty * 6, j0 = tx * 6;

    if (m == 0) {
        for (int idx = tid; idx < 9216; idx += 256) {
            int i = idx / 96, d = idx % 96;
            bufA[idx]        = Wq[i * 768 + h * 96 + d];
            bufB[d * TP + i] = Wk[i * 768 + h * 96 + d];
        }
        __syncthreads();
        ull acc[6][3];
#pragma unroll
        for (int i = 0; i < 6; ++i) for (int p = 0; p < 3; ++p) acc[i][p] = 0ULL;
        gemm96<1, TP>(bufA, bufB, i0, j0, acc);   // M = Wq_h Wk_h^T
#pragma unroll
        for (int i = 0; i < 6; ++i)
#pragma unroll
            for (int p = 0; p < 3; ++p) {
                float2 f = unpk(acc[i][p]);
                // store transposed: g_M[j][c] = M[c][j] * inv
                g_M[h * 9216 + (j0 + 2 * p)     * 96 + (i0 + i)] = f.x * inv;
                g_M[h * 9216 + (j0 + 2 * p + 1) * 96 + (i0 + i)] = f.y * inv;
            }
        if (tid < 96) {
            float a = 0.f, c = 0.f;
            for (int d = 0; d < 96; ++d) {
                a += bufA[tid * 96 + d] * bk[h * 96 + d];
                c += bufB[d * TP + tid] * bq[h * 96 + d];
            }
            g_u[h * 96 + tid] = a * inv;
            g_w[h * 96 + tid] = c * inv;
        }
        if (tid == 0) {
            float cs = 0.f;
            for (int d = 0; d < 96; ++d) cs += bq[h * 96 + d] * bk[h * 96 + d];
            g_cc[h] = cs * inv;
        }
        if (h == 0 && tid >= 128 && tid < 224) {
            int c = tid - 128;
            float s = bo[c];
            for (int j = 0; j < 768; ++j) s += bv[j] * Wo[j * 96 + c];
            g_bp[c] = s;
        }
    } else {
        for (int idx = tid; idx < 9216; idx += 256) {
            int i = idx / 96, d = idx % 96;
            bufA[idx] = Wv[i * 768 + h * 96 + d];
            bufB[idx] = Wo[h * 9216 + idx];
        }
        __syncthreads();
        ull acc[6][3];
#pragma unroll
        for (int i = 0; i < 6; ++i) for (int p = 0; p < 3; ++p) acc[i][p] = 0ULL;
        gemm96<1, 96>(bufA, bufB, i0, j0, acc);   // N = Wv_h Wo_h
#pragma unroll
        for (int i = 0; i < 6; ++i)
#pragma unroll
            for (int p = 0; p < 3; ++p) {
                float2 f = unpk(acc[i][p]);
                g_N[h * 9216 + (j0 + 2 * p)     * 96 + (i0 + i)] = f.x;
                g_N[h * 9216 + (j0 + 2 * p + 1) * 96 + (i0 + i)] = f.y;
            }
    }
}

// ---- 3) Attention via tf32 mma.sync. 384 thr, 12 warps, warp = 16 rows x 48 cols.
__global__ __launch_bounds__(384, 1)
void attn_kernel() {
    const int b = blockIdx.x, h = blockIdx.y;
    extern __shared__ uint32 smu[];
    uint32* tS = smu;              // t (tf32, row-major), later X2^T
    uint32* W  = smu + 96 * PT;    // M^T, later P
    uint32* Y  = smu + 2 * 96 * PT;// X1, later N^T
    float* rv  = (float*)(smu + 3 * 96 * PT);
    float* zv  = rv + 96;
    float* uv  = zv + 96;
    float* wvv = uv + 96;
    float* pmx = wvv + 96;   // [2][96]
    float* psm = pmx + 192;  // [2][96]

    const int tid = threadIdx.x;
    const int lane = tid & 31, wid = tid >> 5;
    const int r0 = (wid >> 1) * 16, c0 = (wid & 1) * 48;
    const int g = lane >> 2, tg = lane & 3;
    const float NEGINF = __int_as_float(0xff800000);

    // stage t + M^T (tf32)
    {
        const float* xb = g_xn + b * 9216;
        const float* Mh = g_M + h * 9216;
        for (int idx = tid; idx < 9216; idx += 384) {
            int rr = idx / 96, cc = idx - rr * 96;
            tS[rr * PT + cc] = f2tf(xb[idx]);
            W [rr * PT + cc] = f2tf(Mh[idx]);
        }
        if (tid < 96) { uv[tid] = g_u[h * 96 + tid]; wvv[tid] = g_w[h * 96 + tid]; }
    }
    __syncthreads();

    // r, z (row dots on row-major t)
    if (tid < 96) {
        float a = 0.f;
        for (int c = 0; c < 96; ++c) a += __uint_as_float(tS[tid * PT + c]) * uv[c];
        rv[tid] = a;
    } else if (tid < 192) {
        const int j = tid - 96;
        float a = 0.f;
        for (int c = 0; c < 96; ++c) a += __uint_as_float(tS[j * PT + c]) * wvv[c];
        zv[j] = a;
    }

    // GEMM1: X1 = t * M  (A=tS, B=W[M^T])
    {
        float c[6][4];
#pragma unroll
        for (int n = 0; n < 6; ++n) for (int q = 0; q < 4; ++q) c[n][q] = 0.f;
        wgemm(tS, W, r0, c0, lane, c);
#pragma unroll
        for (int n = 0; n < 6; ++n) {
            const int col = c0 + n * 8 + 2 * tg, row = r0 + g;
            Y[row * PT + col]           = f2tf(c[n][0]);
            Y[row * PT + col + 1]       = f2tf(c[n][1]);
            Y[(row + 8) * PT + col]     = f2tf(c[n][2]);
            Y[(row + 8) * PT + col + 1] = f2tf(c[n][3]);
        }
    }
    __syncthreads();   // S0: X1 ready; M^T dead

    // GEMM2: S = X1 * t^T  (A=Y, B=tS) + causal softmax
    float sv[6][4];
    {
#pragma unroll
        for (int n = 0; n < 6; ++n) for (int q = 0; q < 4; ++q) sv[n][q] = 0.f;
        wgemm(Y, tS, r0, c0, lane, sv);
    }
    const int i0r = r0 + g, i1r = r0 + g + 8;
    const float ccv = g_cc[h];
    {
        const float ri0 = rv[i0r] + ccv, ri1 = rv[i1r] + ccv;
        float m0 = NEGINF, m1 = NEGINF;
#pragma unroll
        for (int n = 0; n < 6; ++n) {
            const int j0 = c0 + n * 8 + 2 * tg, j1 = j0 + 1;
            float v00 = (j0 <= i0r) ? sv[n][0] + ri0 + zv[j0] : NEGINF;
            float v01 = (j1 <= i0r) ? sv[n][1] + ri0 + zv[j1] : NEGINF;
            float v10 = (j0 <= i1r) ? sv[n][2] + ri1 + zv[j0] : NEGINF;
            float v11 = (j1 <= i1r) ? sv[n][3] + ri1 + zv[j1] : NEGINF;
            sv[n][0] = v00; sv[n][1] = v01; sv[n][2] = v10; sv[n][3] = v11;
            m0 = fmaxf(m0, fmaxf(v00, v01));
            m1 = fmaxf(m1, fmaxf(v10, v11));
        }
        m0 = fmaxf(m0, __shfl_xor_sync(0xffffffffu, m0, 1));
        m0 = fmaxf(m0, __shfl_xor_sync(0xffffffffu, m0, 2));
        m1 = fmaxf(m1, __shfl_xor_sync(0xffffffffu, m1, 1));
        m1 = fmaxf(m1, __shfl_xor_sync(0xffffffffu, m1, 2));
        if (tg == 0) { pmx[(wid & 1) * 96 + i0r] = m0; pmx[(wid & 1) * 96 + i1r] = m1; }
    }
    __syncthreads();   // S1: partial maxes ready; Y (X1) dead

    {
        const float m0f = fmaxf(pmx[i0r], pmx[96 + i0r]);
        const float m1f = fmaxf(pmx[i1r], pmx[96 + i1r]);
        float s0 = 0.f, s1 = 0.f;
#pragma unroll
        for (int n = 0; n < 6; ++n) {
            float e0 = __expf(sv[n][0] - m0f), e1 = __expf(sv[n][1] - m0f);
            float e2 = __expf(sv[n][2] - m1f), e3 = __expf(sv[n][3] - m1f);
            sv[n][0] = e0; sv[n][1] = e1; sv[n][2] = e2; sv[n][3] = e3;
            s0 += e0 + e1; s1 += e2 + e3;
        }
        s0 += __shfl_xor_sync(0xffffffffu, s0, 1);
        s0 += __shfl_xor_sync(0xffffffffu, s0, 2);
        s1 += __shfl_xor_sync(0xffffffffu, s1, 1);
        s1 += __shfl_xor_sync(0xffffffffu, s1, 2);
        if (tg == 0) { psm[(wid & 1) * 96 + i0r] = s0; psm[(wid & 1) * 96 + i1r] = s1; }
    }
    // stage N^T into Y (dead since S1)
    {
        const float* Nh = g_N + h * 9216;
        for (int idx = tid; idx < 9216; idx += 384) {
            int rr = idx / 96, cc = idx - rr * 96;
            Y[rr * PT + cc] = f2tf(Nh[idx]);
        }
    }
    __syncthreads();   // S2: sums + N^T ready

    {
        const float is0 = 1.0f / (psm[i0r] + psm[96 + i0r]);
        const float is1 = 1.0f / (psm[i1r] + psm[96 + i1r]);
#pragma unroll
        for (int n = 0; n < 6; ++n) {
            const int col = c0 + n * 8 + 2 * tg;
            W[i0r * PT + col]     = f2tf(sv[n][0] * is0);
            W[i0r * PT + col + 1] = f2tf(sv[n][1] * is0);
            W[i1r * PT + col]     = f2tf(sv[n][2] * is1);
            W[i1r * PT + col + 1] = f2tf(sv[n][3] * is1);
        }
    }

    // GEMM3: X2 = t * N  (A=tS, B=Y[N^T]); store X2^T into tS
    {
        float c[6][4];
#pragma unroll
        for (int n = 0; n < 6; ++n) for (int q = 0; q < 4; ++q) c[n][q] = 0.f;
        wgemm(tS, Y, r0, c0, lane, c);
        __syncthreads();   // S3: all t reads done; all P stores done
#pragma unroll
        for (int n = 0; n < 6; ++n) {
            const int col = c0 + n * 8 + 2 * tg, row = r0 + g;
            tS[col * PT + row]           = f2tf(c[n][0]);
            tS[(col + 1) * PT + row]     = f2tf(c[n][1]);
            tS[col * PT + row + 8]       = f2tf(c[n][2]);
            tS[(col + 1) * PT + row + 8] = f2tf(c[n][3]);
        }
    }
    __syncthreads();   // S4: X2^T ready

    // GEMM4: AV = P * X2  (A=W[P], B=tS[X2^T]) -> g_part
    {
        float c[6][4];
#pragma unroll
        for (int n = 0; n < 6; ++n) for (int q = 0; q < 4; ++q) c[n][q] = 0.f;
        wgemm(W, tS, r0, c0, lane, c);
        float* dst = g_part + (h * 96 + b) * 9216;
#pragma unroll
        for (int n = 0; n < 6; ++n) {
            const int l0 = c0 + n * 8 + 2 * tg, row = r0 + g;
            *(float2*)(dst + row * 96 + l0)       = make_float2(c[n][0], c[n][1]);
            *(float2*)(dst + (row + 8) * 96 + l0) = make_float2(c[n][2], c[n][3]);
        }
    }
}

// ---- 4) Head reduction + bias
__global__ void reduce_kernel() {
    const int idx = blockIdx.x * 256 + threadIdx.x;
    float4 a = ((const float4*)g_bp)[idx % 24];
#pragma unroll
    for (int h = 0; h < 8; ++h) {
        float4 p = ((const float4*)g_part)[h * 221184 + idx];
        a.x += p.x; a.y += p.y; a.z += p.z; a.w += p.w;
    }
    ((float4*)g_O)[idx] = a;
}

// ---- 5) Broadcast residual
__global__ __launch_bounds__(384)
void bcast_kernel(float* __restrict__ out) {
    __shared__ __align__(16) float O_s[9216];
    const int bt = blockIdx.x, j = blockIdx.y;
    const int tid = threadIdx.x;
    const float4* Og = (const float4*)(g_O + j * 9216);
    float4* Os4 = (float4*)O_s;
#pragma unroll
    for (int r = 0; r < 6; ++r) Os4[tid + r * 384] = Og[tid + r * 384];
    const int b_i = tid / 24;
    const int q   = tid - b_i * 24;
    const int bg  = bt * 16 + b_i;
    const float4 xnv = *(const float4*)(g_xn + (size_t)bg * 9216 + j * 96 + q * 4);
    __syncthreads();
    float* dst = out + ((size_t)bg * 96 + (size_t)j) * 9216 + q * 4;
#pragma unroll 8
    for (int s = 0; s < 96; ++s) {
        float4 o = Os4[s * 24 + q];
        float4 v = make_float4(o.x + xnv.x, o.y + xnv.y, o.z + xnv.z, o.w + xnv.w);
        __stcs((float4*)(dst + s * 96), v);
    }
}

extern "C" void kernel_launch(void* const* d_in, const int* in_sizes, int n_in,
                              void* d_out, int out_size) {
    const float* x     = (const float*)d_in[0];
    const float* Wq    = (const float*)d_in[1];
    const float* bq    = (const float*)d_in[2];
    const float* Wk    = (const float*)d_in[3];
    const float* bk    = (const float*)d_in[4];
    const float* Wv    = (const float*)d_in[5];
    const float* bv    = (const float*)d_in[6];
    const float* Wo    = (const float*)d_in[7];
    const float* bo    = (const float*)d_in[8];
    const float* gamma = (const float*)d_in[9];
    const float* beta  = (const float*)d_in[10];
    float* out = (float*)d_out;

    const int pre_smem  = (9216 + 96 * TP) * 4;
    const int attn_smem = (3 * 96 * PT + 96 * 4 + 192 * 2) * 4;   // 118,272 B
    cudaFuncSetAttribute(pre_kernel,  cudaFuncAttributeMaxDynamicSharedMemorySize, pre_smem);
    cudaFuncSetAttribute(attn_kernel, cudaFuncAttributeMaxDynamicSharedMemorySize, attn_smem);

    gn_kernel<<<dim3(96, 8), 128>>>(x, gamma, beta);
    pre_kernel<<<dim3(8, 2), 256, pre_smem>>>(Wq, bq, Wk, bk, Wv, bv, Wo, bo);
    attn_kernel<<<dim3(96, 8), 384, attn_smem>>>();
    reduce_kernel<<<864, 256>>>();
    bcast_kernel<<<dim3(6, 96), 384>>>(out);
}

// round 10
// speedup vs baseline: 1.5730x; 1.1443x over previous
#include <cuda_runtime.h>
#include <math.h>

#define TP 98
#define PT 100
typedef unsigned long long ull;
typedef unsigned uint32;

__device__ __align__(16) float g_xn[96*96*96];
__device__ __align__(16) float g_M[8*96*96];   // transposed + tf32-rounded: [h][j][c]
__device__ __align__(16) float g_N[8*96*96];   // transposed + tf32-rounded: [h][l][c]
__device__ __align__(16) float g_u[8*96];
__device__ __align__(16) float g_w[8*96];
__device__ __align__(16) float g_cc[8];
__device__ __align__(16) float g_bp[96];
__device__ __align__(16) float g_part[8*96*96*96];
__device__ __align__(16) float g_O[96*96*96];

__device__ __forceinline__ ull pack2(float a) {
    ull r; asm("mov.b64 %0, {%1, %2};" : "=l"(r) : "f"(a), "f"(a)); return r;
}
__device__ __forceinline__ ull fma2(ull a, ull b, ull c) {
    ull d; asm("fma.rn.f32x2 %0, %1, %2, %3;" : "=l"(d) : "l"(a), "l"(b), "l"(c)); return d;
}
__device__ __forceinline__ float2 unpk(ull p) {
    float2 f; asm("mov.b64 {%0, %1}, %2;" : "=f"(f.x), "=f"(f.y) : "l"(p)); return f;
}
__device__ __forceinline__ uint32 f2tf(float f) {
    uint32 r; asm("cvt.rna.tf32.f32 %0, %1;" : "=r"(r) : "f"(f)); return r;
}
__device__ __forceinline__ void mma8(float c[4], uint32 a0, uint32 a1, uint32 a2, uint32 a3,
                                     uint32 b0, uint32 b1) {
    asm("mma.sync.aligned.m16n8k8.row.col.f32.tf32.tf32.f32 "
        "{%0,%1,%2,%3},{%4,%5,%6,%7},{%8,%9},{%0,%1,%2,%3};"
        : "+f"(c[0]), "+f"(c[1]), "+f"(c[2]), "+f"(c[3])
        : "r"(a0), "r"(a1), "r"(a2), "r"(a3), "r"(b0), "r"(b1));
}

// Warp GEMM: C(16x48) = A(rows r0..r0+15, k=0..95) x B([n][k] layout), both pitch PT.
__device__ __forceinline__ void wgemm(const uint32* __restrict__ A,
                                      const uint32* __restrict__ B,
                                      int r0, int c0, int lane, float c[6][4]) {
    const int g = lane >> 2, tg = lane & 3;
    const uint32* Ap = A + (r0 + g) * PT + tg;
    const uint32* Bp = B + (c0 + g) * PT + tg;
#pragma unroll
    for (int k8 = 0; k8 < 12; ++k8) {
        const int kb = k8 * 8;
        uint32 a0 = Ap[kb], a1 = Ap[8 * PT + kb], a2 = Ap[kb + 4], a3 = Ap[8 * PT + kb + 4];
#pragma unroll
        for (int n = 0; n < 6; ++n) {
            uint32 b0 = Bp[n * 8 * PT + kb], b1 = Bp[n * 8 * PT + kb + 4];
            mma8(c[n], a0, a1, a2, a3, b0, b1);
        }
    }
}

// FFMA2 GEMM for pre
template<int AMODE, int PB>
__device__ __forceinline__ void gemm96(const float* __restrict__ A,
                                       const float* __restrict__ B,
                                       int i0, int j0, ull acc[6][3]) {
    const float* Bj = B + j0;
#pragma unroll 2
    for (int k = 0; k < 96; k += 2) {
        ull b0[3], b1[3];
#pragma unroll
        for (int p = 0; p < 3; ++p) {
            b0[p] = *(const ull*)(Bj + k * PB + 2 * p);
            b1[p] = *(const ull*)(Bj + (k + 1) * PB + 2 * p);
        }
        ull a0[6], a1[6];
        if (AMODE == 0) {
#pragma unroll
            for (int ii = 0; ii < 3; ++ii) {
                float2 f0 = *(const float2*)(A + k * TP + i0 + 2 * ii);
                float2 f1 = *(const float2*)(A + (k + 1) * TP + i0 + 2 * ii);
                a0[2*ii] = pack2(f0.x); a0[2*ii+1] = pack2(f0.y);
                a1[2*ii] = pack2(f1.x); a1[2*ii+1] = pack2(f1.y);
            }
        } else {
#pragma unroll
            for (int i = 0; i < 6; ++i) {
                float2 f = *(const float2*)(A + (i0 + i) * 96 + k);
                a0[i] = pack2(f.x); a1[i] = pack2(f.y);
            }
        }
#pragma unroll
        for (int i = 0; i < 6; ++i)
#pragma unroll
            for (int p = 0; p < 3; ++p)
                acc[i][p] = fma2(a0[i], b0[p], acc[i][p]);
#pragma unroll
        for (int i = 0; i < 6; ++i)
#pragma unroll
            for (int p = 0; p < 3; ++p)
                acc[i][p] = fma2(a1[i], b1[p], acc[i][p]);
    }
}

// ---- 1) GroupNorm
__global__ void gn_kernel(const float* __restrict__ x,
                          const float* __restrict__ gamma,
                          const float* __restrict__ beta) {
    const int b = blockIdx.x, g = blockIdx.y, tid = threadIdx.x;
    const float* xp = x + b * 9216 + g * 1152;
    float vals[9], sum = 0.f, sq = 0.f;
#pragma unroll
    for (int t = 0; t < 9; ++t) {
        float v = xp[tid + t * 128];
        vals[t] = v; sum += v; sq += v * v;
    }
    __shared__ float s1[128], s2[128];
    s1[tid] = sum; s2[tid] = sq;
    __syncthreads();
    for (int o = 64; o > 0; o >>= 1) {
        if (tid < o) { s1[tid] += s1[tid + o]; s2[tid] += s2[tid + o]; }
        __syncthreads();
    }
    const float mean = s1[0] * (1.f / 1152.f);
    const float var  = s2[0] * (1.f / 1152.f) - mean * mean;
    const float rstd = rsqrtf(var + 1e-5f);
#pragma unroll
    for (int t = 0; t < 9; ++t) {
        int e = tid + t * 128;
        int ch = g * 12 + e / 96;
        g_xn[b * 9216 + g * 1152 + e] = (vals[t] - mean) * rstd * gamma[ch] + beta[ch];
    }
}

// ---- 2) Precompute (stores M^T, N^T tf32-rounded for the mma B-layout)
__global__ __launch_bounds__(256, 1)
void pre_kernel(const float* __restrict__ Wq, const float* __restrict__ bq,
                const float* __restrict__ Wk, const float* __restrict__ bk,
                const float* __restrict__ Wv, const float* __restrict__ bv,
                const float* __restrict__ Wo, const float* __restrict__ bo) {
    const int h = blockIdx.x, m = blockIdx.y, tid = threadIdx.x;
    extern __shared__ float sm[];
    float* bufA = sm;
    float* bufB = sm + 9216;
    const float inv = rsqrtf(96.0f);
    const int tx = tid & 15, ty = tid >> 4;
    const int i0 = ty * 6, j0 = tx * 6;

    if (m == 0) {
        for (int idx = tid; idx < 9216; idx += 256) {
            int i = idx / 96, d = idx % 96;
            bufA[idx]        = Wq[i * 768 + h * 96 + d];
            bufB[d * TP + i] = Wk[i * 768 + h * 96 + d];
        }
        __syncthreads();
        ull acc[6][3];
#pragma unroll
        for (int i = 0; i < 6; ++i) for (int p = 0; p < 3; ++p) acc[i][p] = 0ULL;
        gemm96<1, TP>(bufA, bufB, i0, j0, acc);   // M = Wq_h Wk_h^T
#pragma unroll
        for (int i = 0; i < 6; ++i)
#pragma unroll
            for (int p = 0; p < 3; ++p) {
                float2 f = unpk(acc[i][p]);
                g_M[h * 9216 + (j0 + 2 * p)     * 96 + (i0 + i)] = __uint_as_float(f2tf(f.x * inv));
                g_M[h * 9216 + (j0 + 2 * p + 1) * 96 + (i0 + i)] = __uint_as_float(f2tf(f.y * inv));
            }
        if (tid < 96) {
            float a = 0.f, c = 0.f;
            for (int d = 0; d < 96; ++d) {
                a += bufA[tid * 96 + d] * bk[h * 96 + d];
                c += bufB[d * TP + tid] * bq[h * 96 + d];
            }
            g_u[h * 96 + tid] = a * inv;
            g_w[h * 96 + tid] = c * inv;
        }
        if (tid == 0) {
            float cs = 0.f;
            for (int d = 0; d < 96; ++d) cs += bq[h * 96 + d] * bk[h * 96 + d];
            g_cc[h] = cs * inv;
        }
        if (h == 0 && tid >= 128 && tid < 224) {
            int c = tid - 128;
            float s = bo[c];
            for (int j = 0; j < 768; ++j) s += bv[j] * Wo[j * 96 + c];
            g_bp[c] = s;
        }
    } else {
        for (int idx = tid; idx < 9216; idx += 256) {
            int i = idx / 96, d = idx % 96;
            bufA[idx] = Wv[i * 768 + h * 96 + d];
            bufB[idx] = Wo[h * 9216 + idx];
        }
        __syncthreads();
        ull acc[6][3];
#pragma unroll
        for (int i = 0; i < 6; ++i) for (int p = 0; p < 3; ++p) acc[i][p] = 0ULL;
        gemm96<1, 96>(bufA, bufB, i0, j0, acc);   // N = Wv_h Wo_h
#pragma unroll
        for (int i = 0; i < 6; ++i)
#pragma unroll
            for (int p = 0; p < 3; ++p) {
                float2 f = unpk(acc[i][p]);
                g_N[h * 9216 + (j0 + 2 * p)     * 96 + (i0 + i)] = __uint_as_float(f2tf(f.x));
                g_N[h * 9216 + (j0 + 2 * p + 1) * 96 + (i0 + i)] = __uint_as_float(f2tf(f.y));
            }
    }
}

// ---- 3) Attention via tf32 mma.sync, occ=2 (side vectors live in buffer padding cols)
__global__ __launch_bounds__(384, 2)
void attn_kernel() {
    const int b = blockIdx.x, h = blockIdx.y;
    extern __shared__ uint32 smu[];
    uint32* tS = smu;              // t (tf32), later X2^T ; pad cols 96..99 = rv,zv,uv,wv
    uint32* W  = smu + 96 * PT;    // M^T, later P        ; pad cols 96..99 = pmx[2],psm[2]
    uint32* Y  = smu + 2 * 96 * PT;// X1, later N^T
    float* tSf = (float*)tS;
    float* Wf  = (float*)W;
#define RV(i)      tSf[(i) * PT + 96]
#define ZV(i)      tSf[(i) * PT + 97]
#define UV(i)      tSf[(i) * PT + 98]
#define WV(i)      tSf[(i) * PT + 99]
#define PMX(hf, i) Wf[(i) * PT + 96 + (hf)]
#define PSM(hf, i) Wf[(i) * PT + 98 + (hf)]

    const int tid = threadIdx.x;
    const int lane = tid & 31, wid = tid >> 5;
    const int r0 = (wid >> 1) * 16, c0 = (wid & 1) * 48;
    const int g = lane >> 2, tg = lane & 3;
    const float NEGINF = __int_as_float(0xff800000);

    // stage t (cvt) + M^T (pre-rounded copy), float4 loads
    {
        const float4* xb4 = (const float4*)(g_xn + b * 9216);
        const float4* Mh4 = (const float4*)(g_M + h * 9216);
#pragma unroll
        for (int r = 0; r < 6; ++r) {
            int idx = tid + r * 384;            // 2304 float4s
            int rr = idx / 24, q4 = idx - rr * 24;
            float4 xv = xb4[idx];
            uint4 tv = make_uint4(f2tf(xv.x), f2tf(xv.y), f2tf(xv.z), f2tf(xv.w));
            *(uint4*)(tS + rr * PT + q4 * 4) = tv;
            *(float4*)(Wf + rr * PT + q4 * 4) = Mh4[idx];
        }
        if (tid < 96) { UV(tid) = g_u[h * 96 + tid]; WV(tid) = g_w[h * 96 + tid]; }
    }
    __syncthreads();

    // r, z (row dots on row-major t)
    if (tid < 96) {
        float a = 0.f;
        for (int c = 0; c < 96; ++c) a += __uint_as_float(tS[tid * PT + c]) * UV(c);
        RV(tid) = a;
    } else if (tid < 192) {
        const int j = tid - 96;
        float a = 0.f;
        for (int c = 0; c < 96; ++c) a += __uint_as_float(tS[j * PT + c]) * WV(c);
        ZV(j) = a;
    }

    // GEMM1: X1 = t * M  (A=tS, B=W[M^T])
    {
        float c[6][4];
#pragma unroll
        for (int n = 0; n < 6; ++n) for (int q = 0; q < 4; ++q) c[n][q] = 0.f;
        wgemm(tS, W, r0, c0, lane, c);
#pragma unroll
        for (int n = 0; n < 6; ++n) {
            const int col = c0 + n * 8 + 2 * tg, row = r0 + g;
            Y[row * PT + col]           = f2tf(c[n][0]);
            Y[row * PT + col + 1]       = f2tf(c[n][1]);
            Y[(row + 8) * PT + col]     = f2tf(c[n][2]);
            Y[(row + 8) * PT + col + 1] = f2tf(c[n][3]);
        }
    }
    __syncthreads();   // S0: X1 ready; M^T dead

    // GEMM2: S = X1 * t^T  (A=Y, B=tS) + causal softmax
    float sv[6][4];
    {
#pragma unroll
        for (int n = 0; n < 6; ++n) for (int q = 0; q < 4; ++q) sv[n][q] = 0.f;
        wgemm(Y, tS, r0, c0, lane, sv);
    }
    const int i0r = r0 + g, i1r = r0 + g + 8;
    const float ccv = g_cc[h];
    {
        const float ri0 = RV(i0r) + ccv, ri1 = RV(i1r) + ccv;
        float m0 = NEGINF, m1 = NEGINF;
#pragma unroll
        for (int n = 0; n < 6; ++n) {
            const int j0 = c0 + n * 8 + 2 * tg, j1 = j0 + 1;
            float v00 = (j0 <= i0r) ? sv[n][0] + ri0 + ZV(j0) : NEGINF;
            float v01 = (j1 <= i0r) ? sv[n][1] + ri0 + ZV(j1) : NEGINF;
            float v10 = (j0 <= i1r) ? sv[n][2] + ri1 + ZV(j0) : NEGINF;
            float v11 = (j1 <= i1r) ? sv[n][3] + ri1 + ZV(j1) : NEGINF;
            sv[n][0] = v00; sv[n][1] = v01; sv[n][2] = v10; sv[n][3] = v11;
            m0 = fmaxf(m0, fmaxf(v00, v01));
            m1 = fmaxf(m1, fmaxf(v10, v11));
        }
        m0 = fmaxf(m0, __shfl_xor_sync(0xffffffffu, m0, 1));
        m0 = fmaxf(m0, __shfl_xor_sync(0xffffffffu, m0, 2));
        m1 = fmaxf(m1, __shfl_xor_sync(0xffffffffu, m1, 1));
        m1 = fmaxf(m1, __shfl_xor_sync(0xffffffffu, m1, 2));
        if (tg == 0) { PMX(wid & 1, i0r) = m0; PMX(wid & 1, i1r) = m1; }
    }
    __syncthreads();   // S1: partial maxes ready; Y (X1) dead

    {
        const float m0f = fmaxf(PMX(0, i0r), PMX(1, i0r));
        const float m1f = fmaxf(PMX(0, i1r), PMX(1, i1r));
        float s0 = 0.f, s1 = 0.f;
#pragma unroll
        for (int n = 0; n < 6; ++n) {
            float e0 = __expf(sv[n][0] - m0f), e1 = __expf(sv[n][1] - m0f);
            float e2 = __expf(sv[n][2] - m1f), e3 = __expf(sv[n][3] - m1f);
            sv[n][0] = e0; sv[n][1] = e1; sv[n][2] = e2; sv[n][3] = e3;
            s0 += e0 + e1; s1 += e2 + e3;
        }
        s0 += __shfl_xor_sync(0xffffffffu, s0, 1);
        s0 += __shfl_xor_sync(0xffffffffu, s0, 2);
        s1 += __shfl_xor_sync(0xffffffffu, s1, 1);
        s1 += __shfl_xor_sync(0xffffffffu, s1, 2);
        if (tg == 0) { PSM(wid & 1, i0r) = s0; PSM(wid & 1, i1r) = s1; }
    }
    // stage N^T into Y (pre-rounded copy)
    {
        const float4* Nh4 = (const float4*)(g_N + h * 9216);
        float* Yf = (float*)Y;
#pragma unroll
        for (int r = 0; r < 6; ++r) {
            int idx = tid + r * 384;
            int rr = idx / 24, q4 = idx - rr * 24;
            *(float4*)(Yf + rr * PT + q4 * 4) = Nh4[idx];
        }
    }
    __syncthreads();   // S2: sums + N^T ready

    {
        const float is0 = 1.0f / (PSM(0, i0r) + PSM(1, i0r));
        const float is1 = 1.0f / (PSM(0, i1r) + PSM(1, i1r));
#pragma unroll
        for (int n = 0; n < 6; ++n) {
            const int col = c0 + n * 8 + 2 * tg;
            W[i0r * PT + col]     = f2tf(sv[n][0] * is0);
            W[i0r * PT + col + 1] = f2tf(sv[n][1] * is0);
            W[i1r * PT + col]     = f2tf(sv[n][2] * is1);
            W[i1r * PT + col + 1] = f2tf(sv[n][3] * is1);
        }
    }

    // GEMM3: X2 = t * N  (A=tS, B=Y[N^T]); store X2^T into tS
    {
        float c[6][4];
#pragma unroll
        for (int n = 0; n < 6; ++n) for (int q = 0; q < 4; ++q) c[n][q] = 0.f;
        wgemm(tS, Y, r0, c0, lane, c);
        __syncthreads();   // S3: all t reads done; all P stores done
#pragma unroll
        for (int n = 0; n < 6; ++n) {
            const int col = c0 + n * 8 + 2 * tg, row = r0 + g;
            tS[col * PT + row]           = f2tf(c[n][0]);
            tS[(col + 1) * PT + row]     = f2tf(c[n][1]);
            tS[col * PT + row + 8]       = f2tf(c[n][2]);
            tS[(col + 1) * PT + row + 8] = f2tf(c[n][3]);
        }
    }
    __syncthreads();   // S4: X2^T ready

    // GEMM4: AV = P * X2  (A=W[P], B=tS[X2^T]) -> g_part
    {
        float c[6][4];
#pragma unroll
        for (int n = 0; n < 6; ++n) for (int q = 0; q < 4; ++q) c[n][q] = 0.f;
        wgemm(W, tS, r0, c0, lane, c);
        float* dst = g_part + (h * 96 + b) * 9216;
#pragma unroll
        for (int n = 0; n < 6; ++n) {
            const int l0 = c0 + n * 8 + 2 * tg, row = r0 + g;
            *(float2*)(dst + row * 96 + l0)       = make_float2(c[n][0], c[n][1]);
            *(float2*)(dst + (row + 8) * 96 + l0) = make_float2(c[n][2], c[n][3]);
        }
    }
#undef RV
#undef ZV
#undef UV
#undef WV
#undef PMX
#undef PSM
}

// ---- 4) Head reduction + bias
__global__ void reduce_kernel() {
    const int idx = blockIdx.x * 256 + threadIdx.x;
    float4 a = ((const float4*)g_bp)[idx % 24];
#pragma unroll
    for (int h = 0; h < 8; ++h) {
        float4 p = ((const float4*)g_part)[h * 221184 + idx];
        a.x += p.x; a.y += p.y; a.z += p.z; a.w += p.w;
    }
    ((float4*)g_O)[idx] = a;
}

// ---- 5) Broadcast residual
__global__ __launch_bounds__(384)
void bcast_kernel(float* __restrict__ out) {
    __shared__ __align__(16) float O_s[9216];
    const int bt = blockIdx.x, j = blockIdx.y;
    const int tid = threadIdx.x;
    const float4* Og = (const float4*)(g_O + j * 9216);
    float4* Os4 = (float4*)O_s;
#pragma unroll
    for (int r = 0; r < 6; ++r) Os4[tid + r * 384] = Og[tid + r * 384];
    const int b_i = tid / 24;
    const int q   = tid - b_i * 24;
    const int bg  = bt * 16 + b_i;
    const float4 xnv = *(const float4*)(g_xn + (size_t)bg * 9216 + j * 96 + q * 4);
    __syncthreads();
    float* dst = out + ((size_t)bg * 96 + (size_t)j) * 9216 + q * 4;
#pragma unroll 8
    for (int s = 0; s < 96; ++s) {
        float4 o = Os4[s * 24 + q];
        float4 v = make_float4(o.x + xnv.x, o.y + xnv.y, o.z + xnv.z, o.w + xnv.w);
        __stcs((float4*)(dst + s * 96), v);
    }
}

extern "C" void kernel_launch(void* const* d_in, const int* in_sizes, int n_in,
                              void* d_out, int out_size) {
    const float* x     = (const float*)d_in[0];
    const float* Wq    = (const float*)d_in[1];
    const float* bq    = (const float*)d_in[2];
    const float* Wk    = (const float*)d_in[3];
    const float* bk    = (const float*)d_in[4];
    const float* Wv    = (const float*)d_in[5];
    const float* bv    = (const float*)d_in[6];
    const float* Wo    = (const float*)d_in[7];
    const float* bo    = (const float*)d_in[8];
    const float* gamma = (const float*)d_in[9];
    const float* beta  = (const float*)d_in[10];
    float* out = (float*)d_out;

    const int pre_smem  = (9216 + 96 * TP) * 4;
    const int attn_smem = 3 * 96 * PT * 4;   // 115,200 B -> 2 CTAs/SM
    cudaFuncSetAttribute(pre_kernel,  cudaFuncAttributeMaxDynamicSharedMemorySize, pre_smem);
    cudaFuncSetAttribute(attn_kernel, cudaFuncAttributeMaxDynamicSharedMemorySize, attn_smem);

    gn_kernel<<<dim3(96, 8), 128>>>(x, gamma, beta);
    pre_kernel<<<dim3(8, 2), 256, pre_smem>>>(Wq, bq, Wk, bk, Wv, bv, Wo, bo);
    attn_kernel<<<dim3(96, 8), 384, attn_smem>>>();
    reduce_kernel<<<864, 256>>>();
    bcast_kernel<<<dim3(6, 96), 384>>>(out);
}